// round 2
// baseline (speedup 1.0000x reference)
#include <cuda_runtime.h>
#include <math.h>

#define NL 8
#define NE 8
#define ND 256
#define NB 16384
#define NH1 64
#define NH2 32

#define TM 32
#define NTH 256

// ---- shared memory layout (float offsets) ----
// xsT   [256][36]  : x tile transposed (d-major, padded)       9216
// big   region     : Ws[32][132] / W2s[64][68] | h1sT[128][36] ; W3s[32][260] overlays all
// h2sT  [64][36]   : scaled h2 transposed                      2304
// wsoft [32][8]    : softmax weights
// b1s[128] b2s[64] b3s[256]
#define OFF_XST   0
#define OFF_BIG   9216
#define OFF_H1    (OFF_BIG + 4352)            // h1sT after Ws/W2s region
#define OFF_H2S   (OFF_BIG + 8960)
#define OFF_WSOFT (OFF_H2S + 2304)
#define OFF_B1    (OFF_WSOFT + 256)
#define OFF_B2    (OFF_B1 + 128)
#define OFF_B3    (OFF_B2 + 64)
#define SMEM_FLOATS (OFF_B3 + 256)            // 21184 floats
#define SMEM_BYTES  (SMEM_FLOATS * 4)         // 84736 bytes

__global__ void __launch_bounds__(NTH, 2)
moe_fused_kernel(const float* __restrict__ src,
                 const float* __restrict__ W1, const float* __restrict__ b1,
                 const float* __restrict__ W2, const float* __restrict__ b2,
                 const float* __restrict__ W3, const float* __restrict__ b3,
                 const float* __restrict__ masks,
                 float* __restrict__ out)
{
    extern __shared__ float sm[];
    float* xsT   = sm + OFF_XST;   // [d][36] rows r in 0..31
    float* Ws    = sm + OFF_BIG;   // [k][132]
    float* W2s   = sm + OFF_BIG;   // [h][68]
    float* h1sT  = sm + OFF_H1;    // [h'][36]
    float* W3s   = sm + OFF_BIG;   // [k][260]
    float* h2sT  = sm + OFF_H2S;   // [j'][36]
    float* wsoft = sm + OFF_WSOFT; // [r][8]
    float* b1s   = sm + OFF_B1;
    float* b2s   = sm + OFF_B2;
    float* b3s   = sm + OFF_B3;

    const int tid = threadIdx.x;
    const int rowbase = blockIdx.x * TM;
    const int rg = tid >> 5;   // row group: rows 4*rg .. 4*rg+3
    const int cg = tid & 31;   // col group

    // ---- load x tile, transposed into xsT (conflict-free float2 pattern) ----
    {
        const int r = (tid >> 2) & 31;
        const float* srcp = src + (size_t)(rowbase + r) * ND;
        #pragma unroll
        for (int m = 0; m < 16; m++) {
            int idx = tid + 256 * m;
            int d2 = (idx & 3) + 4 * (idx >> 7);   // 0..127
            float2 v = *(const float2*)(srcp + 2 * d2);
            xsT[(2 * d2 + 0) * 36 + r] = v.x;
            xsT[(2 * d2 + 1) * 36 + r] = v.y;
        }
    }
    __syncthreads();

    float xacc[4][8];   // persistent next-x accumulators: rows 4rg+i, cols 8cg+j

    for (int l = 0; l < NL; l++) {
        // ---- softmax weights for this layer ----
        if (tid < TM) {
            const float* mrow = masks + ((size_t)l * NB + rowbase + tid) * NE;
            float m0[8]; float mx = -1e30f;
            #pragma unroll
            for (int e = 0; e < 8; e++) { m0[e] = mrow[e]; mx = fmaxf(mx, m0[e]); }
            float s = 0.f;
            #pragma unroll
            for (int e = 0; e < 8; e++) { m0[e] = expf(m0[e] - mx); s += m0[e]; }
            s = 1.f / s;
            #pragma unroll
            for (int e = 0; e < 8; e++) wsoft[tid * 8 + e] = m0[e] * s;
        }
        #pragma unroll
        for (int i = 0; i < 4; i++)
            #pragma unroll
            for (int j = 0; j < 8; j++) xacc[i][j] = 0.f;

        for (int ep = 0; ep < 4; ep++) {        // expert pairs
            const int e0 = ep * 2;
            const float* W1p = W1 + (size_t)(l * NE + e0) * NH1 * ND;  // [128][256]

            // ================= Phase A: GEMM1 (pair) h1 = relu(x*W1^T + b1) =================
            float hacc[4][4];
            #pragma unroll
            for (int i = 0; i < 4; i++)
                #pragma unroll
                for (int j = 0; j < 4; j++) hacc[i][j] = 0.f;

            float2 wreg[8];
            // prefetch k-chunk 0
            #pragma unroll
            for (int m = 0; m < 8; m++) {
                int idx = tid + 256 * m;
                int h  = (idx >> 2) & 127;
                int k2 = (idx & 3) + 4 * (idx >> 9);
                wreg[m] = *(const float2*)(W1p + h * ND + 2 * k2);
            }
            for (int kc = 0; kc < 8; kc++) {
                __syncthreads();   // Ws region free
                #pragma unroll
                for (int m = 0; m < 8; m++) {
                    int idx = tid + 256 * m;
                    int h  = (idx >> 2) & 127;
                    int k2 = (idx & 3) + 4 * (idx >> 9);
                    Ws[(2 * k2 + 0) * 132 + h] = wreg[m].x;
                    Ws[(2 * k2 + 1) * 132 + h] = wreg[m].y;
                }
                if (kc == 0 && tid < 128) b1s[tid] = b1[(size_t)(l * NE + e0) * NH1 + tid];
                __syncthreads();
                if (kc < 7) {   // prefetch next chunk (latency hidden behind compute)
                    #pragma unroll
                    for (int m = 0; m < 8; m++) {
                        int idx = tid + 256 * m;
                        int h  = (idx >> 2) & 127;
                        int k2 = (idx & 3) + 4 * (idx >> 9);
                        wreg[m] = *(const float2*)(W1p + h * ND + (kc + 1) * 32 + 2 * k2);
                    }
                }
                const float* xp = xsT + (kc * 32) * 36 + 4 * rg;
                const float* wp = Ws + 4 * cg;
                #pragma unroll
                for (int k = 0; k < 32; k++) {
                    float4 xt = *(const float4*)(xp + k * 36);
                    float4 wt = *(const float4*)(wp + k * 132);
                    float xr[4] = {xt.x, xt.y, xt.z, xt.w};
                    float wr[4] = {wt.x, wt.y, wt.z, wt.w};
                    #pragma unroll
                    for (int i = 0; i < 4; i++)
                        #pragma unroll
                        for (int j = 0; j < 4; j++)
                            hacc[i][j] += xr[i] * wr[j];
                }
            }
            // epilogue: bias + relu -> h1sT (transposed)
            #pragma unroll
            for (int j = 0; j < 4; j++) {
                int h = 4 * cg + j;
                float bb = b1s[h];
                #pragma unroll
                for (int i = 0; i < 4; i++) {
                    float v = fmaxf(hacc[i][j] + bb, 0.f);
                    h1sT[h * 36 + 4 * rg + i] = v;
                }
            }
            __syncthreads();

            // ================= Phase B: GEMM2 (pair, block-diagonal) =================
            {
                const float* W2p = W2 + (size_t)(l * NE + e0) * NH2 * NH1;
                #pragma unroll
                for (int m = 0; m < 8; m++) {
                    int idx = tid + 256 * m;
                    int jp = (idx >> 2) & 63;
                    int h2 = (idx & 3) + 4 * ((idx >> 8) & 7);
                    float2 v = *(const float2*)(W2p + jp * NH1 + 2 * h2);
                    W2s[(2 * h2 + 0) * 68 + jp] = v.x;
                    W2s[(2 * h2 + 1) * 68 + jp] = v.y;
                }
                if (tid < 64) b2s[tid] = b2[(size_t)(l * NE + e0) * NH2 + tid];
            }
            __syncthreads();
            {
                const int el2 = cg >> 4;   // which expert of the pair this thread's cols belong to
                float h2acc[4][2];
                #pragma unroll
                for (int i = 0; i < 4; i++) { h2acc[i][0] = 0.f; h2acc[i][1] = 0.f; }
                const float* h1b = h1sT + el2 * 64 * 36 + 4 * rg;
                const float* w2b = W2s + 2 * cg;
                #pragma unroll
                for (int h = 0; h < 64; h++) {
                    float4 ht = *(const float4*)(h1b + h * 36);
                    float2 wt = *(const float2*)(w2b + h * 68);
                    float hr[4] = {ht.x, ht.y, ht.z, ht.w};
                    #pragma unroll
                    for (int i = 0; i < 4; i++) {
                        h2acc[i][0] += hr[i] * wt.x;
                        h2acc[i][1] += hr[i] * wt.y;
                    }
                }
                // epilogue: bias, relu, pre-scale by softmax weight, store transposed
                #pragma unroll
                for (int jj = 0; jj < 2; jj++) {
                    int jp = 2 * cg + jj;
                    float bb = b2s[jp];
                    #pragma unroll
                    for (int i = 0; i < 4; i++) {
                        int r = 4 * rg + i;
                        float wgt = wsoft[r * 8 + e0 + el2];
                        h2sT[jp * 36 + r] = fmaxf(h2acc[i][jj] + bb, 0.f) * wgt;
                    }
                }
            }
            __syncthreads();

            // ================= Phase C: GEMM3 per expert, accumulate into xacc =================
            for (int el = 0; el < 2; el++) {
                const float* W3p = W3 + (size_t)(l * NE + e0 + el) * ND * NH2;  // [256][32]
                #pragma unroll
                for (int m = 0; m < 16; m++) {
                    int idx = tid + 256 * m;
                    int d  = (idx >> 2) & 255;
                    int k2 = (idx & 3) + 4 * (idx >> 10);
                    float2 v = *(const float2*)(W3p + d * NH2 + 2 * k2);
                    W3s[(2 * k2 + 0) * 260 + d] = v.x;
                    W3s[(2 * k2 + 1) * 260 + d] = v.y;
                }
                b3s[tid] = b3[(size_t)(l * NE + e0 + el) * ND + tid];
                __syncthreads();
                {
                    const float* h2b = h2sT + el * 32 * 36 + 4 * rg;
                    const float* w3b = W3s + 8 * cg;
                    #pragma unroll
                    for (int k = 0; k < 32; k++) {
                        float4 ht = *(const float4*)(h2b + k * 36);
                        float4 w0 = *(const float4*)(w3b + k * 260);
                        float4 w1 = *(const float4*)(w3b + k * 260 + 4);
                        float hr[4] = {ht.x, ht.y, ht.z, ht.w};
                        float wr[8] = {w0.x, w0.y, w0.z, w0.w, w1.x, w1.y, w1.z, w1.w};
                        #pragma unroll
                        for (int i = 0; i < 4; i++)
                            #pragma unroll
                            for (int j = 0; j < 8; j++)
                                xacc[i][j] += hr[i] * wr[j];
                    }
                    // weighted b3 contribution: sum_e w[r,e] * b3[e,c]
                    #pragma unroll
                    for (int i = 0; i < 4; i++) {
                        float wgt = wsoft[(4 * rg + i) * 8 + e0 + el];
                        #pragma unroll
                        for (int j = 0; j < 8; j++)
                            xacc[i][j] += wgt * b3s[8 * cg + j];
                    }
                }
                __syncthreads();
            }
        } // expert pairs

        // ---- layer output: either to global (last layer) or back into xsT ----
        if (l == NL - 1) {
            #pragma unroll
            for (int i = 0; i < 4; i++) {
                float* op = out + (size_t)(rowbase + 4 * rg + i) * ND + 8 * cg;
                float4 a = make_float4(xacc[i][0], xacc[i][1], xacc[i][2], xacc[i][3]);
                float4 b = make_float4(xacc[i][4], xacc[i][5], xacc[i][6], xacc[i][7]);
                *(float4*)op = a;
                *(float4*)(op + 4) = b;
            }
        } else {
            #pragma unroll
            for (int i = 0; i < 4; i++) {
                int r = 4 * rg + i;
                #pragma unroll
                for (int jj = 0; jj < 8; jj++) {
                    int j = (jj + cg) & 7;   // stagger to reduce bank conflicts
                    xsT[(8 * cg + j) * 36 + r] = xacc[i][j];
                }
            }
            __syncthreads();
        }
    } // layers
}

extern "C" void kernel_launch(void* const* d_in, const int* in_sizes, int n_in,
                              void* d_out, int out_size)
{
    const float* src   = (const float*)d_in[0];
    const float* W1    = (const float*)d_in[1];
    const float* b1    = (const float*)d_in[2];
    const float* W2    = (const float*)d_in[3];
    const float* b2    = (const float*)d_in[4];
    const float* W3    = (const float*)d_in[5];
    const float* b3    = (const float*)d_in[6];
    const float* masks = (const float*)d_in[7];
    float* out = (float*)d_out;

    (void)in_sizes; (void)n_in; (void)out_size;

    cudaFuncSetAttribute(moe_fused_kernel,
                         cudaFuncAttributeMaxDynamicSharedMemorySize, SMEM_BYTES);
    moe_fused_kernel<<<NB / TM, NTH, SMEM_BYTES>>>(src, W1, b1, W2, b2, W3, b3, masks, out);
}

// round 4
// speedup vs baseline: 2.6513x; 2.6513x over previous
#include <cuda_runtime.h>
#include <cuda_bf16.h>
#include <cstdint>
#include <math.h>

#define NL 8
#define NE 8
#define ND 256
#define NB 16384
#define TM 128
#define NTH 256

// ---------------- fragment helpers ----------------
__device__ __forceinline__ uint32_t packhi(float a, float b) {
    __nv_bfloat162 t;
    t.x = __float2bfloat16(a);
    t.y = __float2bfloat16(b);
    return *(uint32_t*)&t;
}
__device__ __forceinline__ uint32_t packlo(float a, float b) {
    __nv_bfloat162 t;
    t.x = __float2bfloat16(a - __bfloat162float(__float2bfloat16(a)));
    t.y = __float2bfloat16(b - __bfloat162float(__float2bfloat16(b)));
    return *(uint32_t*)&t;
}

#define MMA(c, ax, ay, az, aw, b0, b1) \
    asm volatile("mma.sync.aligned.m16n8k16.row.col.f32.bf16.bf16.f32 " \
        "{%0,%1,%2,%3},{%4,%5,%6,%7},{%8,%9},{%0,%1,%2,%3};" \
        : "+f"((c)[0]), "+f"((c)[1]), "+f"((c)[2]), "+f"((c)[3]) \
        : "r"(ax), "r"(ay), "r"(az), "r"(aw), "r"(b0), "r"(b1))

// ---------------- global weight-fragment image ----------------
// per (l,e) bytes: Bhi1 32768 | Blo1 32768 | Bhi2 4096 | Blo2 4096 | Bhi3 16384 | Blo3 16384
#define PER_LE 106496
#define B3OFF (64 * PER_LE)
__device__ __align__(16) unsigned char g_w[B3OFF + 8 * 8192];

__global__ void prep_kernel(const float* __restrict__ W1, const float* __restrict__ W2,
                            const float* __restrict__ W3, const float* __restrict__ b3) {
    const int le = blockIdx.x;
    const int t = threadIdx.x;
    unsigned char* base = g_w + (size_t)le * PER_LE;

    const float* W1p = W1 + (size_t)le * 16384;   // [64][256]
    for (int idx = t; idx < 4096; idx += 256) {
        int kt = idx >> 8, nt = (idx >> 5) & 7, ln = idx & 31;
        int n = nt * 8 + ln / 4, k = kt * 16 + (ln % 4) * 2;
        float f00 = W1p[n * 256 + k], f01 = W1p[n * 256 + k + 1];
        float f10 = W1p[n * 256 + k + 8], f11 = W1p[n * 256 + k + 9];
        *(uint2*)(base + idx * 8) = make_uint2(packhi(f00, f01), packhi(f10, f11));
        *(uint2*)(base + 32768 + idx * 8) = make_uint2(packlo(f00, f01), packlo(f10, f11));
    }
    const float* W2p = W2 + (size_t)le * 2048;    // [32][64]
    for (int idx = t; idx < 512; idx += 256) {
        int kt = idx >> 7, nt = (idx >> 5) & 3, ln = idx & 31;
        int n = nt * 8 + ln / 4, k = kt * 16 + (ln % 4) * 2;
        float f00 = W2p[n * 64 + k], f01 = W2p[n * 64 + k + 1];
        float f10 = W2p[n * 64 + k + 8], f11 = W2p[n * 64 + k + 9];
        *(uint2*)(base + 65536 + idx * 8) = make_uint2(packhi(f00, f01), packhi(f10, f11));
        *(uint2*)(base + 69632 + idx * 8) = make_uint2(packlo(f00, f01), packlo(f10, f11));
    }
    const float* W3p = W3 + (size_t)le * 8192;    // [256][32]
    for (int idx = t; idx < 2048; idx += 256) {
        int kt = idx >> 10, nt = (idx >> 5) & 31, ln = idx & 31;
        int n = nt * 8 + ln / 4, k = kt * 16 + (ln % 4) * 2;
        float f00 = W3p[n * 32 + k], f01 = W3p[n * 32 + k + 1];
        float f10 = W3p[n * 32 + k + 8], f11 = W3p[n * 32 + k + 9];
        *(uint2*)(base + 73728 + idx * 8) = make_uint2(packhi(f00, f01), packhi(f10, f11));
        *(uint2*)(base + 90112 + idx * 8) = make_uint2(packlo(f00, f01), packlo(f10, f11));
    }
    if ((le & 7) == 0) {
        int l = le >> 3;
        const float* b3p = b3 + (size_t)l * 2048;  // [8][256]
        unsigned char* bb = g_w + B3OFF + (size_t)l * 8192;
        for (int idx = t; idx < 1024; idx += 256) {
            int nt = idx >> 5, ln = idx & 31;
            int n = nt * 8 + ln / 4, e0 = (ln % 4) * 2;
            float v0 = b3p[e0 * 256 + n], v1 = b3p[(e0 + 1) * 256 + n];
            *(uint32_t*)(bb + idx * 4) = packhi(v0, v1);
            *(uint32_t*)(bb + 4096 + idx * 4) = packlo(v0, v1);
        }
    }
}

// ---------------- smem layout (bytes) ----------------
#define XFRAG 0          // [kt32][rt8][ln32] uint4 = 131072
#define WBUF  131072     // 32768 : W1hi / W1lo / h1frag / W3(hi|lo)
#define W2F   163840     // hi 4096 | lo 4096
#define H2F   172032     // [kt4][rt8][ln32] uint4 = 16384
#define B3F   188416     // hi 4096 | lo 4096
#define WFA   196608     // [rt8][ln32] uint4 = 4096
#define WSOFT 200704     // [128][8] f32 = 4096
#define B1S   204800     // 256
#define B2S   205056     // 128
#define SMEM_BYTES 205184

__device__ __forceinline__ void cpyg(char* dst, const unsigned char* src, int bytes, int tid) {
    const uint4* s = (const uint4*)src;
    uint4* d = (uint4*)dst;
    int n = bytes >> 4;
    for (int i = tid; i < n; i += NTH) d[i] = s[i];
}

__global__ void __launch_bounds__(NTH, 1)
moe_mma_kernel(const float* __restrict__ src,
               const float* __restrict__ b1, const float* __restrict__ b2,
               const float* __restrict__ masks, float* __restrict__ out)
{
    extern __shared__ char smem[];
    const int tid = threadIdx.x;
    const int w = tid >> 5;
    const int ln = tid & 31;
    const int wm4 = w & 3;       // row-block (GEMM1/3)
    const int nh = w >> 2;       // n-half (GEMM1) / n-quarter-pair (GEMM3)
    const int rowbase = blockIdx.x * TM;

    float* b1s = (float*)(smem + B1S);
    float* b2s = (float*)(smem + B2S);
    float* wsoft = (float*)(smem + WSOFT);
    uint32_t* xfrag = (uint32_t*)(smem + XFRAG);

    // ---- initial X -> A-fragment image (hi kt 0..15, lo kt 16..31) ----
    if (tid < TM) {
        const int r = tid;
        const float* sp = src + (size_t)(rowbase + r) * ND;
        const int rhalf = (r & 15) >> 3;
        #pragma unroll 4
        for (int m = 0; m < 128; m++) {
            float f0 = sp[2 * m], f1 = sp[2 * m + 1];
            int kt = m >> 3;
            int lane = 4 * (r & 7) + (m & 3);
            int khalf = (m & 7) >> 2;
            int reg = 2 * khalf + rhalf;
            int slot = ((kt * 8 + (r >> 4)) * 32 + lane) * 4 + reg;
            xfrag[slot] = packhi(f0, f1);
            xfrag[slot + 16 * 8 * 32 * 4] = packlo(f0, f1);
        }
    }

    float xacc[2][16][4];

    for (int l = 0; l < NL; l++) {
        // ---- softmax -> wsoft + wfragA; stage b3 frags ----
        if (tid < TM) {
            const int r = tid;
            const float* mp = masks + ((size_t)l * NB + rowbase + r) * NE;
            float m[8], mx = -1e30f;
            #pragma unroll
            for (int e = 0; e < 8; e++) { m[e] = mp[e]; mx = fmaxf(mx, m[e]); }
            float s = 0.f;
            #pragma unroll
            for (int e = 0; e < 8; e++) { m[e] = expf(m[e] - mx); s += m[e]; }
            s = 1.f / s;
            #pragma unroll
            for (int e = 0; e < 8; e++) { m[e] *= s; wsoft[r * 8 + e] = m[e]; }
            uint32_t* wfa = (uint32_t*)(smem + WFA);
            const int rhalf = (r & 15) >> 3;
            #pragma unroll
            for (int q = 0; q < 4; q++) {
                int ub = (((r >> 4) * 32) + 4 * (r & 7) + q) * 4;
                wfa[ub + rhalf] = packhi(m[2 * q], m[2 * q + 1]);
                wfa[ub + 2 + rhalf] = packlo(m[2 * q], m[2 * q + 1]);
            }
        }
        cpyg(smem + B3F, g_w + B3OFF + (size_t)l * 8192, 8192, tid);
        #pragma unroll
        for (int i = 0; i < 2; i++)
            #pragma unroll
            for (int j = 0; j < 16; j++)
                #pragma unroll
                for (int q = 0; q < 4; q++) xacc[i][j][q] = 0.f;

        for (int e = 0; e < NE; e++) {
            const unsigned char* wp = g_w + (size_t)(l * 8 + e) * PER_LE;

            // ======== GEMM1 ========
            float c1[2][4][4];
            #pragma unroll
            for (int i = 0; i < 2; i++)
                #pragma unroll
                for (int j = 0; j < 4; j++)
                    #pragma unroll
                    for (int q = 0; q < 4; q++) c1[i][j][q] = 0.f;

            __syncthreads();                       // xfrag ready / WBUF free
            cpyg(smem + WBUF, wp, 32768, tid);     // W1 hi frags
            __syncthreads();
            {
                const uint2* wb = (const uint2*)(smem + WBUF);
                #pragma unroll 1
                for (int p = 0; p < 2; p++) {      // Xhi*Whi, Xlo*Whi
                    int ab = p * 16;
                    #pragma unroll
                    for (int kt = 0; kt < 16; kt++) {
                        uint4 a0 = *(const uint4*)(smem + XFRAG + (((ab + kt) * 8 + 2 * wm4) * 32 + ln) * 16);
                        uint4 a1 = *(const uint4*)(smem + XFRAG + (((ab + kt) * 8 + 2 * wm4 + 1) * 32 + ln) * 16);
                        #pragma unroll
                        for (int nt = 0; nt < 4; nt++) {
                            uint2 b = wb[(kt * 8 + 4 * nh + nt) * 32 + ln];
                            MMA(c1[0][nt], a0.x, a0.y, a0.z, a0.w, b.x, b.y);
                            MMA(c1[1][nt], a1.x, a1.y, a1.z, a1.w, b.x, b.y);
                        }
                    }
                }
            }
            __syncthreads();
            cpyg(smem + WBUF, wp + 32768, 32768, tid);     // W1 lo frags
            cpyg(smem + W2F, wp + 65536, 8192, tid);       // W2 hi+lo frags
            if (tid < 64) b1s[tid] = b1[(size_t)(l * 8 + e) * 64 + tid];
            else if (tid < 96) b2s[tid - 64] = b2[(size_t)(l * 8 + e) * 32 + tid - 64];
            __syncthreads();
            {
                const uint2* wb = (const uint2*)(smem + WBUF); // Xhi*Wlo
                #pragma unroll
                for (int kt = 0; kt < 16; kt++) {
                    uint4 a0 = *(const uint4*)(smem + XFRAG + ((kt * 8 + 2 * wm4) * 32 + ln) * 16);
                    uint4 a1 = *(const uint4*)(smem + XFRAG + ((kt * 8 + 2 * wm4 + 1) * 32 + ln) * 16);
                    #pragma unroll
                    for (int nt = 0; nt < 4; nt++) {
                        uint2 b = wb[(kt * 8 + 4 * nh + nt) * 32 + ln];
                        MMA(c1[0][nt], a0.x, a0.y, a0.z, a0.w, b.x, b.y);
                        MMA(c1[1][nt], a1.x, a1.y, a1.z, a1.w, b.x, b.y);
                    }
                }
            }
            __syncthreads();   // WBUF free -> becomes h1frag

            // ---- D1 epilogue: bias+relu, split -> h1 A-frags in WBUF ----
            {
                #pragma unroll
                for (int rt = 0; rt < 2; rt++) {
                    int rtg = 2 * wm4 + rt;
                    #pragma unroll
                    for (int ntp = 0; ntp < 2; ntp++) {
                        float v[2][4];
                        #pragma unroll
                        for (int n2 = 0; n2 < 2; n2++) {
                            int gc = 32 * nh + (2 * ntp + n2) * 8 + (ln & 3) * 2;
                            float bb0 = b1s[gc], bb1 = b1s[gc + 1];
                            float* c = c1[rt][2 * ntp + n2];
                            v[n2][0] = fmaxf(c[0] + bb0, 0.f);
                            v[n2][1] = fmaxf(c[1] + bb1, 0.f);
                            v[n2][2] = fmaxf(c[2] + bb0, 0.f);
                            v[n2][3] = fmaxf(c[3] + bb1, 0.f);
                        }
                        int kt = nh * 2 + ntp;
                        uint4 hi = make_uint4(packhi(v[0][0], v[0][1]), packhi(v[0][2], v[0][3]),
                                              packhi(v[1][0], v[1][1]), packhi(v[1][2], v[1][3]));
                        uint4 lo = make_uint4(packlo(v[0][0], v[0][1]), packlo(v[0][2], v[0][3]),
                                              packlo(v[1][0], v[1][1]), packlo(v[1][2], v[1][3]));
                        *(uint4*)(smem + WBUF + ((kt * 8 + rtg) * 32 + ln) * 16) = hi;
                        *(uint4*)(smem + WBUF + (((kt + 4) * 8 + rtg) * 32 + ln) * 16) = lo;
                    }
                }
            }
            __syncthreads();

            // ======== GEMM2 (warp w: rows 16w, all 32 cols) ========
            float c2[4][4];
            #pragma unroll
            for (int j = 0; j < 4; j++)
                #pragma unroll
                for (int q = 0; q < 4; q++) c2[j][q] = 0.f;
            {
                const uint2* bh = (const uint2*)(smem + W2F);
                const uint2* bl = (const uint2*)(smem + W2F + 4096);
                #pragma unroll
                for (int kt = 0; kt < 4; kt++) {
                    uint4 ah = *(const uint4*)(smem + WBUF + ((kt * 8 + w) * 32 + ln) * 16);
                    uint4 al = *(const uint4*)(smem + WBUF + (((kt + 4) * 8 + w) * 32 + ln) * 16);
                    #pragma unroll
                    for (int nt = 0; nt < 4; nt++) {
                        uint2 b0 = bh[(kt * 4 + nt) * 32 + ln];
                        uint2 b1v = bl[(kt * 4 + nt) * 32 + ln];
                        MMA(c2[nt], ah.x, ah.y, ah.z, ah.w, b0.x, b0.y);
                        MMA(c2[nt], al.x, al.y, al.z, al.w, b0.x, b0.y);
                        MMA(c2[nt], ah.x, ah.y, ah.z, ah.w, b1v.x, b1v.y);
                    }
                }
            }
            __syncthreads();   // h1frag consumed; WBUF free for W3

            // ---- D2 epilogue: bias+relu, *softmax, split -> h2 A-frags ----
            {
                float wg0 = wsoft[(16 * w + ln / 4) * 8 + e];
                float wg1 = wsoft[(16 * w + 8 + ln / 4) * 8 + e];
                #pragma unroll
                for (int ntp = 0; ntp < 2; ntp++) {
                    float v[2][4];
                    #pragma unroll
                    for (int n2 = 0; n2 < 2; n2++) {
                        int gc = (2 * ntp + n2) * 8 + (ln & 3) * 2;
                        float bb0 = b2s[gc], bb1 = b2s[gc + 1];
                        float* c = c2[2 * ntp + n2];
                        v[n2][0] = fmaxf(c[0] + bb0, 0.f) * wg0;
                        v[n2][1] = fmaxf(c[1] + bb1, 0.f) * wg0;
                        v[n2][2] = fmaxf(c[2] + bb0, 0.f) * wg1;
                        v[n2][3] = fmaxf(c[3] + bb1, 0.f) * wg1;
                    }
                    uint4 hi = make_uint4(packhi(v[0][0], v[0][1]), packhi(v[0][2], v[0][3]),
                                          packhi(v[1][0], v[1][1]), packhi(v[1][2], v[1][3]));
                    uint4 lo = make_uint4(packlo(v[0][0], v[0][1]), packlo(v[0][2], v[0][3]),
                                          packlo(v[1][0], v[1][1]), packlo(v[1][2], v[1][3]));
                    *(uint4*)(smem + H2F + ((ntp * 8 + w) * 32 + ln) * 16) = hi;
                    *(uint4*)(smem + H2F + (((ntp + 2) * 8 + w) * 32 + ln) * 16) = lo;
                }
            }
            cpyg(smem + WBUF, wp + 73728, 32768, tid);   // W3 hi|lo frags
            __syncthreads();

            // ======== GEMM3 (warp w: rows 32*wm4.., cols 128*nh..) ========
            {
                const uint2* bh = (const uint2*)(smem + WBUF);
                const uint2* bl = (const uint2*)(smem + WBUF + 16384);
                const uint32_t* b3h = (const uint32_t*)(smem + B3F);
                const uint32_t* b3l = (const uint32_t*)(smem + B3F + 4096);
                #pragma unroll 1
                for (int rt = 0; rt < 2; rt++) {
                    int rtg = 2 * wm4 + rt;
                    uint4 ah0 = *(const uint4*)(smem + H2F + ((0 * 8 + rtg) * 32 + ln) * 16);
                    uint4 ah1 = *(const uint4*)(smem + H2F + ((1 * 8 + rtg) * 32 + ln) * 16);
                    uint4 al0 = *(const uint4*)(smem + H2F + ((2 * 8 + rtg) * 32 + ln) * 16);
                    uint4 al1 = *(const uint4*)(smem + H2F + ((3 * 8 + rtg) * 32 + ln) * 16);
                    uint4 wf = *(const uint4*)(smem + WFA + (rtg * 32 + ln) * 16);
                    #pragma unroll
                    for (int nt = 0; nt < 16; nt++) {
                        int gnt = 16 * nh + nt;
                        uint2 b0 = bh[(0 * 32 + gnt) * 32 + ln];
                        uint2 b1v = bh[(1 * 32 + gnt) * 32 + ln];
                        uint2 b2v = bl[(0 * 32 + gnt) * 32 + ln];
                        uint2 b3v = bl[(1 * 32 + gnt) * 32 + ln];
                        float* cc = xacc[rt][nt];
                        MMA(cc, ah0.x, ah0.y, ah0.z, ah0.w, b0.x, b0.y);
                        MMA(cc, ah1.x, ah1.y, ah1.z, ah1.w, b1v.x, b1v.y);
                        MMA(cc, al0.x, al0.y, al0.z, al0.w, b0.x, b0.y);
                        MMA(cc, al1.x, al1.y, al1.z, al1.w, b1v.x, b1v.y);
                        MMA(cc, ah0.x, ah0.y, ah0.z, ah0.w, b2v.x, b2v.y);
                        MMA(cc, ah1.x, ah1.y, ah1.z, ah1.w, b3v.x, b3v.y);
                        if (e == 0) {   // weighted-b3 term, once per layer
                            uint32_t p3h = b3h[gnt * 32 + ln];
                            uint32_t p3l = b3l[gnt * 32 + ln];
                            MMA(cc, wf.x, wf.y, wf.z, wf.w, p3h, p3h);
                            MMA(cc, wf.x, wf.y, 0u, 0u, p3l, 0u);
                        }
                    }
                }
            }
            __syncthreads();
        } // experts

        // ---- layer end: xacc -> xfrag (or out) ----
        if (l == NL - 1) {
            #pragma unroll
            for (int rt = 0; rt < 2; rt++) {
                int r0 = 32 * wm4 + rt * 16 + ln / 4;
                #pragma unroll
                for (int nt = 0; nt < 16; nt++) {
                    int col = 128 * nh + nt * 8 + (ln & 3) * 2;
                    float* cc = xacc[rt][nt];
                    *(float2*)(out + (size_t)(rowbase + r0) * ND + col) = make_float2(cc[0], cc[1]);
                    *(float2*)(out + (size_t)(rowbase + r0 + 8) * ND + col) = make_float2(cc[2], cc[3]);
                }
            }
        } else {
            #pragma unroll
            for (int rt = 0; rt < 2; rt++) {
                int rtg = 2 * wm4 + rt;
                #pragma unroll
                for (int nt = 0; nt < 16; nt++) {
                    int kt = 8 * nh + nt / 2;
                    float* cc = xacc[rt][nt];
                    int sb = ((kt * 8 + rtg) * 32 + ln) * 4 + 2 * (nt & 1);
                    xfrag[sb] = packhi(cc[0], cc[1]);
                    xfrag[sb + 1] = packhi(cc[2], cc[3]);
                    xfrag[sb + 16 * 8 * 32 * 4] = packlo(cc[0], cc[1]);
                    xfrag[sb + 16 * 8 * 32 * 4 + 1] = packlo(cc[2], cc[3]);
                }
            }
            __syncthreads();
        }
    } // layers
}

extern "C" void kernel_launch(void* const* d_in, const int* in_sizes, int n_in,
                              void* d_out, int out_size)
{
    const float* src   = (const float*)d_in[0];
    const float* W1    = (const float*)d_in[1];
    const float* b1    = (const float*)d_in[2];
    const float* W2    = (const float*)d_in[3];
    const float* b2    = (const float*)d_in[4];
    const float* W3    = (const float*)d_in[5];
    const float* b3    = (const float*)d_in[6];
    const float* masks = (const float*)d_in[7];
    float* out = (float*)d_out;
    (void)in_sizes; (void)n_in; (void)out_size;

    prep_kernel<<<64, 256>>>(W1, W2, W3, b3);
    cudaFuncSetAttribute(moe_mma_kernel,
                         cudaFuncAttributeMaxDynamicSharedMemorySize, SMEM_BYTES);
    moe_mma_kernel<<<NB / TM, NTH, SMEM_BYTES>>>(src, b1, b2, masks, out);
}

// round 5
// speedup vs baseline: 2.9200x; 1.1013x over previous
#include <cuda_runtime.h>
#include <cuda_bf16.h>
#include <cstdint>
#include <math.h>

#define NL 8
#define NE 8
#define ND 256
#define NB 16384
#define TM 128
#define NTH 512

// ---------------- helpers ----------------
__device__ __forceinline__ uint32_t smem_to_u32(const void* p) {
    uint32_t a;
    asm("{ .reg .u64 t; cvta.to.shared.u64 t, %1; cvt.u32.u64 %0, t; }" : "=r"(a) : "l"(p));
    return a;
}
__device__ __forceinline__ uint32_t packhi(float a, float b) {
    __nv_bfloat162 t;
    t.x = __float2bfloat16(a);
    t.y = __float2bfloat16(b);
    return *(uint32_t*)&t;
}
__device__ __forceinline__ uint32_t packlo(float a, float b) {
    __nv_bfloat162 t;
    t.x = __float2bfloat16(a - __bfloat162float(__float2bfloat16(a)));
    t.y = __float2bfloat16(b - __bfloat162float(__float2bfloat16(b)));
    return *(uint32_t*)&t;
}

#define MMA(c, ax, ay, az, aw, b0, b1) \
    asm volatile("mma.sync.aligned.m16n8k16.row.col.f32.bf16.bf16.f32 " \
        "{%0,%1,%2,%3},{%4,%5,%6,%7},{%8,%9},{%0,%1,%2,%3};" \
        : "+f"((c)[0]), "+f"((c)[1]), "+f"((c)[2]), "+f"((c)[3]) \
        : "r"(ax), "r"(ay), "r"(az), "r"(aw), "r"(b0), "r"(b1))

#define CP_COMMIT asm volatile("cp.async.commit_group;" ::: "memory")
#define CP_WAIT(n) asm volatile("cp.async.wait_group %0;" :: "n"(n) : "memory")

__device__ __forceinline__ void cpya(uint32_t dst, const unsigned char* src, int bytes, int tid) {
    for (int i = tid * 16; i < bytes; i += NTH * 16)
        asm volatile("cp.async.cg.shared.global [%0], [%1], 16;" :: "r"(dst + i), "l"(src + i));
}

// ---------------- global weight-fragment image ----------------
// per (l,e) bytes: Bhi1 32768 | Blo1 32768 | Bhi2 4096 | Blo2 4096 | Bhi3 16384 | Blo3 16384
#define PER_LE 106496
#define B3OFF (64 * PER_LE)
__device__ __align__(16) unsigned char g_w[B3OFF + 8 * 8192];

__global__ void prep_kernel(const float* __restrict__ W1, const float* __restrict__ W2,
                            const float* __restrict__ W3, const float* __restrict__ b3) {
    const int le = blockIdx.x;
    const int t = threadIdx.x;
    unsigned char* base = g_w + (size_t)le * PER_LE;

    const float* W1p = W1 + (size_t)le * 16384;   // [64][256]
    for (int idx = t; idx < 4096; idx += 256) {
        int kt = idx >> 8, nt = (idx >> 5) & 7, ln = idx & 31;
        int n = nt * 8 + ln / 4, k = kt * 16 + (ln % 4) * 2;
        float f00 = W1p[n * 256 + k], f01 = W1p[n * 256 + k + 1];
        float f10 = W1p[n * 256 + k + 8], f11 = W1p[n * 256 + k + 9];
        *(uint2*)(base + idx * 8) = make_uint2(packhi(f00, f01), packhi(f10, f11));
        *(uint2*)(base + 32768 + idx * 8) = make_uint2(packlo(f00, f01), packlo(f10, f11));
    }
    const float* W2p = W2 + (size_t)le * 2048;    // [32][64]
    for (int idx = t; idx < 512; idx += 256) {
        int kt = idx >> 7, nt = (idx >> 5) & 3, ln = idx & 31;
        int n = nt * 8 + ln / 4, k = kt * 16 + (ln % 4) * 2;
        float f00 = W2p[n * 64 + k], f01 = W2p[n * 64 + k + 1];
        float f10 = W2p[n * 64 + k + 8], f11 = W2p[n * 64 + k + 9];
        *(uint2*)(base + 65536 + idx * 8) = make_uint2(packhi(f00, f01), packhi(f10, f11));
        *(uint2*)(base + 69632 + idx * 8) = make_uint2(packlo(f00, f01), packlo(f10, f11));
    }
    const float* W3p = W3 + (size_t)le * 8192;    // [256][32]
    for (int idx = t; idx < 2048; idx += 256) {
        int kt = idx >> 10, nt = (idx >> 5) & 31, ln = idx & 31;
        int n = nt * 8 + ln / 4, k = kt * 16 + (ln % 4) * 2;
        float f00 = W3p[n * 32 + k], f01 = W3p[n * 32 + k + 1];
        float f10 = W3p[n * 32 + k + 8], f11 = W3p[n * 32 + k + 9];
        *(uint2*)(base + 73728 + idx * 8) = make_uint2(packhi(f00, f01), packhi(f10, f11));
        *(uint2*)(base + 90112 + idx * 8) = make_uint2(packlo(f00, f01), packlo(f10, f11));
    }
    if ((le & 7) == 0) {
        int l = le >> 3;
        const float* b3p = b3 + (size_t)l * 2048;  // [8][256]
        unsigned char* bb = g_w + B3OFF + (size_t)l * 8192;
        for (int idx = t; idx < 1024; idx += 256) {
            int nt = idx >> 5, ln = idx & 31;
            int n = nt * 8 + ln / 4, e0 = (ln % 4) * 2;
            float v0 = b3p[e0 * 256 + n], v1 = b3p[(e0 + 1) * 256 + n];
            *(uint32_t*)(bb + idx * 4) = packhi(v0, v1);
            *(uint32_t*)(bb + 4096 + idx * 4) = packlo(v0, v1);
        }
    }
}

// ---------------- smem layout (bytes) ----------------
#define XFRAG 0          // [kt32][rt8][ln32] uint4 = 131072 (hi kt0-15, lo kt16-31)
#define BUFA  131072     // 32768
#define BUFB  163840     // 32768
#define W2F   196608     // hi 4096 | lo 4096
#define H2F   204800     // 16384
#define WFA   221184     // 4096
#define WSOFT 225280     // [128][8] f32
#define B1S   229376     // 256
#define B2S   229632     // 128
#define SMEM_BYTES 229760
#define XLO 65536        // byte offset of lo-half of xfrag

__global__ void __launch_bounds__(NTH, 1)
moe_mma_kernel(const float* __restrict__ src,
               const float* __restrict__ b1, const float* __restrict__ b2,
               const float* __restrict__ masks, float* __restrict__ out)
{
    extern __shared__ char smem[];
    const uint32_t sbase = smem_to_u32(smem);
    const int tid = threadIdx.x;
    const int w = tid >> 5;
    const int ln = tid & 31;
    const int wm4 = w & 3;       // rowblock (G1/G3)
    const int nq = w >> 2;       // n-quarter (G1/G3)
    const int rb = w >> 1;       // rowblock (G2)
    const int nhf = w & 1;       // n-half (G2)
    const int rowbase = blockIdx.x * TM;

    float* b1s = (float*)(smem + B1S);
    float* b2s = (float*)(smem + B2S);
    float* wsoft = (float*)(smem + WSOFT);
    uint32_t* xfrag = (uint32_t*)(smem + XFRAG);

    // prologue: prefetch first W1hi into BUFA
    cpya(sbase + BUFA, g_w, 32768, tid);
    CP_COMMIT;

    // initial X -> A-fragment image
    if (tid < TM) {
        const int r = tid;
        const float* sp = src + (size_t)(rowbase + r) * ND;
        const int rhalf = (r & 15) >> 3;
        #pragma unroll 4
        for (int m = 0; m < 128; m++) {
            float f0 = sp[2 * m], f1 = sp[2 * m + 1];
            int kt = m >> 3;
            int lane = 4 * (r & 7) + (m & 3);
            int khalf = (m & 7) >> 2;
            int reg = 2 * khalf + rhalf;
            int slot = ((kt * 8 + (r >> 4)) * 32 + lane) * 4 + reg;
            xfrag[slot] = packhi(f0, f1);
            xfrag[slot + (XLO >> 2)] = packlo(f0, f1);
        }
    }

    uint32_t Poff = BUFA, Qoff = BUFB;
    float xacc[2][8][4];

    for (int l = 0; l < NL; l++) {
        if (tid < TM) {
            const int r = tid;
            const float* mp = masks + ((size_t)l * NB + rowbase + r) * NE;
            float m[8], mx = -1e30f;
            #pragma unroll
            for (int e = 0; e < 8; e++) { m[e] = mp[e]; mx = fmaxf(mx, m[e]); }
            float s = 0.f;
            #pragma unroll
            for (int e = 0; e < 8; e++) { m[e] = expf(m[e] - mx); s += m[e]; }
            s = 1.f / s;
            #pragma unroll
            for (int e = 0; e < 8; e++) { m[e] *= s; wsoft[r * 8 + e] = m[e]; }
            uint32_t* wfa = (uint32_t*)(smem + WFA);
            const int rhalf = (r & 15) >> 3;
            #pragma unroll
            for (int q = 0; q < 4; q++) {
                int ub = (((r >> 4) * 32) + 4 * (r & 7) + q) * 4;
                wfa[ub + rhalf] = packhi(m[2 * q], m[2 * q + 1]);
                wfa[ub + 2 + rhalf] = packlo(m[2 * q], m[2 * q + 1]);
            }
        }
        #pragma unroll
        for (int i = 0; i < 2; i++)
            #pragma unroll
            for (int j = 0; j < 8; j++)
                #pragma unroll
                for (int q = 0; q < 4; q++) xacc[i][j][q] = 0.f;

        for (int e = 0; e < NE; e++) {
            const int idx = l * 8 + e;
            const unsigned char* wp = g_w + (size_t)idx * PER_LE;
            const unsigned char* wn = g_w + (size_t)(idx < 63 ? idx + 1 : 63) * PER_LE;

            CP_WAIT(0);
            __syncthreads();           // P has W1hi; all prior readers done
            cpya(Qoff + sbase, wp + 32768, 32768, tid);   // W1lo -> Q
            cpya(sbase + W2F, wp + 65536, 8192, tid);     // W2 hi+lo
            CP_COMMIT;
            if (tid < 64) b1s[tid] = b1[(size_t)idx * 64 + tid];
            else if (tid < 96) b2s[tid - 64] = b2[(size_t)idx * 32 + tid - 64];

            // ---- G1 fused hi passes: (Xhi+Xlo) * W1hi ----
            float c1[2][2][4];
            #pragma unroll
            for (int i = 0; i < 2; i++)
                #pragma unroll
                for (int j = 0; j < 2; j++)
                    #pragma unroll
                    for (int q = 0; q < 4; q++) c1[i][j][q] = 0.f;
            {
                const char* Pp = smem + Poff;
                #pragma unroll
                for (int kt = 0; kt < 16; kt++) {
                    const char* xb = smem + XFRAG + ((kt * 8 + 2 * wm4) * 32 + ln) * 16;
                    uint4 a0h = *(const uint4*)xb;
                    uint4 a1h = *(const uint4*)(xb + 512);
                    uint4 a0l = *(const uint4*)(xb + XLO);
                    uint4 a1l = *(const uint4*)(xb + XLO + 512);
                    #pragma unroll
                    for (int nt = 0; nt < 2; nt++) {
                        uint2 b = *(const uint2*)(Pp + ((kt * 8 + 2 * nq + nt) * 32 + ln) * 8);
                        MMA(c1[0][nt], a0h.x, a0h.y, a0h.z, a0h.w, b.x, b.y);
                        MMA(c1[1][nt], a1h.x, a1h.y, a1h.z, a1h.w, b.x, b.y);
                        MMA(c1[0][nt], a0l.x, a0l.y, a0l.z, a0l.w, b.x, b.y);
                        MMA(c1[1][nt], a1l.x, a1l.y, a1l.z, a1l.w, b.x, b.y);
                    }
                }
            }
            __syncthreads();           // all done reading P
            cpya(Poff + sbase, wp + 73728, 32768, tid);   // W3 -> P
            CP_COMMIT;
            CP_WAIT(1);                // Q (W1lo) + W2F ready; W3 in flight
            __syncthreads();

            // ---- G1 pass3: Xhi * W1lo ----
            {
                const char* Qp = smem + Qoff;
                #pragma unroll
                for (int kt = 0; kt < 16; kt++) {
                    const char* xb = smem + XFRAG + ((kt * 8 + 2 * wm4) * 32 + ln) * 16;
                    uint4 a0h = *(const uint4*)xb;
                    uint4 a1h = *(const uint4*)(xb + 512);
                    #pragma unroll
                    for (int nt = 0; nt < 2; nt++) {
                        uint2 b = *(const uint2*)(Qp + ((kt * 8 + 2 * nq + nt) * 32 + ln) * 8);
                        MMA(c1[0][nt], a0h.x, a0h.y, a0h.z, a0h.w, b.x, b.y);
                        MMA(c1[1][nt], a1h.x, a1h.y, a1h.z, a1h.w, b.x, b.y);
                    }
                }
            }
            __syncthreads();           // all done reading Q (W1lo)

            // ---- D1 epilogue -> h1 frags into Q ----
            {
                char* Qp = smem + Qoff;
                #pragma unroll
                for (int rt = 0; rt < 2; rt++) {
                    int rtg = 2 * wm4 + rt;
                    float v[2][4];
                    #pragma unroll
                    for (int nt = 0; nt < 2; nt++) {
                        int gc = 16 * nq + nt * 8 + (ln & 3) * 2;
                        float bb0 = b1s[gc], bb1 = b1s[gc + 1];
                        float* c = c1[rt][nt];
                        v[nt][0] = fmaxf(c[0] + bb0, 0.f);
                        v[nt][1] = fmaxf(c[1] + bb1, 0.f);
                        v[nt][2] = fmaxf(c[2] + bb0, 0.f);
                        v[nt][3] = fmaxf(c[3] + bb1, 0.f);
                    }
                    uint4 hi = make_uint4(packhi(v[0][0], v[0][1]), packhi(v[0][2], v[0][3]),
                                          packhi(v[1][0], v[1][1]), packhi(v[1][2], v[1][3]));
                    uint4 lo = make_uint4(packlo(v[0][0], v[0][1]), packlo(v[0][2], v[0][3]),
                                          packlo(v[1][0], v[1][1]), packlo(v[1][2], v[1][3]));
                    *(uint4*)(Qp + ((nq * 8 + rtg) * 32 + ln) * 16) = hi;
                    *(uint4*)(Qp + (((nq + 4) * 8 + rtg) * 32 + ln) * 16) = lo;
                }
            }
            __syncthreads();           // h1 visible

            // ---- G2: h1 (Q) x W2 ----
            float c2[2][4];
            #pragma unroll
            for (int j = 0; j < 2; j++)
                #pragma unroll
                for (int q = 0; q < 4; q++) c2[j][q] = 0.f;
            {
                const char* Qp = smem + Qoff;
                #pragma unroll
                for (int kt = 0; kt < 4; kt++) {
                    uint4 ah = *(const uint4*)(Qp + ((kt * 8 + rb) * 32 + ln) * 16);
                    uint4 al = *(const uint4*)(Qp + (((kt + 4) * 8 + rb) * 32 + ln) * 16);
                    #pragma unroll
                    for (int nt = 0; nt < 2; nt++) {
                        int ntg = 2 * nhf + nt;
                        uint2 bh = *(const uint2*)(smem + W2F + ((kt * 4 + ntg) * 32 + ln) * 8);
                        uint2 bl = *(const uint2*)(smem + W2F + 4096 + ((kt * 4 + ntg) * 32 + ln) * 8);
                        MMA(c2[nt], ah.x, ah.y, ah.z, ah.w, bh.x, bh.y);
                        MMA(c2[nt], al.x, al.y, al.z, al.w, bh.x, bh.y);
                        MMA(c2[nt], ah.x, ah.y, ah.z, ah.w, bl.x, bl.y);
                    }
                }
            }
            // ---- D2 epilogue -> h2 frags into H2F ----
            {
                float wg0 = wsoft[(16 * rb + ln / 4) * 8 + e];
                float wg1 = wsoft[(16 * rb + 8 + ln / 4) * 8 + e];
                float v[2][4];
                #pragma unroll
                for (int nt = 0; nt < 2; nt++) {
                    int gc = 16 * nhf + nt * 8 + (ln & 3) * 2;
                    float bb0 = b2s[gc], bb1 = b2s[gc + 1];
                    float* c = c2[nt];
                    v[nt][0] = fmaxf(c[0] + bb0, 0.f) * wg0;
                    v[nt][1] = fmaxf(c[1] + bb1, 0.f) * wg0;
                    v[nt][2] = fmaxf(c[2] + bb0, 0.f) * wg1;
                    v[nt][3] = fmaxf(c[3] + bb1, 0.f) * wg1;
                }
                uint4 hi = make_uint4(packhi(v[0][0], v[0][1]), packhi(v[0][2], v[0][3]),
                                      packhi(v[1][0], v[1][1]), packhi(v[1][2], v[1][3]));
                uint4 lo = make_uint4(packlo(v[0][0], v[0][1]), packlo(v[0][2], v[0][3]),
                                      packlo(v[1][0], v[1][1]), packlo(v[1][2], v[1][3]));
                *(uint4*)(smem + H2F + ((nhf * 8 + rb) * 32 + ln) * 16) = hi;
                *(uint4*)(smem + H2F + (((nhf + 2) * 8 + rb) * 32 + ln) * 16) = lo;
            }
            __syncthreads();           // h2 visible; h1 (Q) dead
            cpya(Qoff + sbase, wn, 32768, tid);   // next W1hi -> Q
            CP_COMMIT;
            CP_WAIT(1);                // W3 (P) ready; next-W1hi in flight
            __syncthreads();

            // ---- G3: h2 x W3 -> xacc ----
            {
                const char* Pp = smem + Poff;
                const unsigned char* gb3 = g_w + B3OFF + (size_t)l * 8192;
                #pragma unroll 1
                for (int rt = 0; rt < 2; rt++) {
                    int rtg = 2 * wm4 + rt;
                    uint4 ah0 = *(const uint4*)(smem + H2F + ((0 * 8 + rtg) * 32 + ln) * 16);
                    uint4 ah1 = *(const uint4*)(smem + H2F + ((1 * 8 + rtg) * 32 + ln) * 16);
                    uint4 al0 = *(const uint4*)(smem + H2F + ((2 * 8 + rtg) * 32 + ln) * 16);
                    uint4 al1 = *(const uint4*)(smem + H2F + ((3 * 8 + rtg) * 32 + ln) * 16);
                    uint4 wf = *(const uint4*)(smem + WFA + (rtg * 32 + ln) * 16);
                    #pragma unroll
                    for (int nt = 0; nt < 8; nt++) {
                        int gnt = 8 * nq + nt;
                        uint2 b0 = *(const uint2*)(Pp + ((0 * 32 + gnt) * 32 + ln) * 8);
                        uint2 b1v = *(const uint2*)(Pp + ((32 + gnt) * 32 + ln) * 8);
                        uint2 b2v = *(const uint2*)(Pp + 16384 + ((0 * 32 + gnt) * 32 + ln) * 8);
                        uint2 b3v = *(const uint2*)(Pp + 16384 + ((32 + gnt) * 32 + ln) * 8);
                        float* cc = xacc[rt][nt];
                        MMA(cc, ah0.x, ah0.y, ah0.z, ah0.w, b0.x, b0.y);
                        MMA(cc, ah1.x, ah1.y, ah1.z, ah1.w, b1v.x, b1v.y);
                        MMA(cc, al0.x, al0.y, al0.z, al0.w, b0.x, b0.y);
                        MMA(cc, al1.x, al1.y, al1.z, al1.w, b1v.x, b1v.y);
                        MMA(cc, ah0.x, ah0.y, ah0.z, ah0.w, b2v.x, b2v.y);
                        MMA(cc, ah1.x, ah1.y, ah1.z, ah1.w, b3v.x, b3v.y);
                        if (e == 0) {
                            uint32_t p3h = *(const uint32_t*)(gb3 + (gnt * 32 + ln) * 4);
                            uint32_t p3l = *(const uint32_t*)(gb3 + 4096 + (gnt * 32 + ln) * 4);
                            MMA(cc, wf.x, wf.y, wf.z, wf.w, p3h, p3h);
                            MMA(cc, wf.x, wf.y, 0u, 0u, p3l, 0u);
                        }
                    }
                }
            }
            // swap buffer roles
            uint32_t t2 = Poff; Poff = Qoff; Qoff = t2;
        } // experts

        // ---- layer end: xacc -> xfrag or out ----
        if (l == NL - 1) {
            #pragma unroll
            for (int rt = 0; rt < 2; rt++) {
                int r0 = 32 * wm4 + rt * 16 + ln / 4;
                #pragma unroll
                for (int nt = 0; nt < 8; nt++) {
                    int col = 64 * nq + nt * 8 + (ln & 3) * 2;
                    float* cc = xacc[rt][nt];
                    *(float2*)(out + (size_t)(rowbase + r0) * ND + col) = make_float2(cc[0], cc[1]);
                    *(float2*)(out + (size_t)(rowbase + r0 + 8) * ND + col) = make_float2(cc[2], cc[3]);
                }
            }
        } else {
            __syncthreads();   // all G3 reads of xfrag-era data done (xfrag last read in G1; safe) 
            #pragma unroll
            for (int rt = 0; rt < 2; rt++) {
                int rtg = 2 * wm4 + rt;
                #pragma unroll
                for (int nt = 0; nt < 8; nt++) {
                    int kt = 4 * nq + (nt >> 1);
                    float* cc = xacc[rt][nt];
                    int sb = ((kt * 8 + rtg) * 32 + ln) * 4 + 2 * (nt & 1);
                    xfrag[sb] = packhi(cc[0], cc[1]);
                    xfrag[sb + 1] = packhi(cc[2], cc[3]);
                    xfrag[sb + (XLO >> 2)] = packlo(cc[0], cc[1]);
                    xfrag[sb + (XLO >> 2) + 1] = packlo(cc[2], cc[3]);
                }
            }
        }
    } // layers
    CP_WAIT(0);   // drain trailing prefetch before exit
}

extern "C" void kernel_launch(void* const* d_in, const int* in_sizes, int n_in,
                              void* d_out, int out_size)
{
    const float* src   = (const float*)d_in[0];
    const float* W1    = (const float*)d_in[1];
    const float* b1    = (const float*)d_in[2];
    const float* W2    = (const float*)d_in[3];
    const float* b2    = (const float*)d_in[4];
    const float* W3    = (const float*)d_in[5];
    const float* b3    = (const float*)d_in[6];
    const float* masks = (const float*)d_in[7];
    float* out = (float*)d_out;
    (void)in_sizes; (void)n_in; (void)out_size;

    prep_kernel<<<64, 256>>>(W1, W2, W3, b3);
    cudaFuncSetAttribute(moe_mma_kernel,
                         cudaFuncAttributeMaxDynamicSharedMemorySize, SMEM_BYTES);
    moe_mma_kernel<<<NB / TM, NTH, SMEM_BYTES>>>(src, b1, b2, masks, out);
}